// round 5
// baseline (speedup 1.0000x reference)
#include <cuda_runtime.h>
#include <cuda_bf16.h>
#include <cstdint>

#define BATCH 4096
#define DIM   512
#define N2    (2 * BATCH)   // 8192
#define INV_T 10.0f

#define NTILE 64            // 8192 / 128
#define NTRI  (NTILE * (NTILE + 1) / 2)   // 2080 upper-triangular tiles

// ---------------- device scratch (no allocation allowed) ----------------
__device__ __nv_bfloat16 g_reps[(size_t)N2 * DIM];  // normalized rows, bf16
__device__ float g_pos[BATCH];                      // dot(z_i, z_j) fp32
__device__ float g_denom[N2];                       // masked row sums of exp(sim/T)

// ---------------- helpers ----------------
static __device__ __forceinline__ uint32_t smem_u32(const void* p) {
    uint32_t a;
    asm("{ .reg .u64 t; cvta.to.shared.u64 t, %1; cvt.u32.u64 %0, t; }"
        : "=r"(a) : "l"(p));
    return a;
}

static __device__ __forceinline__ uint32_t sw128(uint32_t o) {
    return o ^ ((o >> 3) & 0x70u);   // SW128 swizzle for 128B rows
}

static __device__ __forceinline__ void ldsm4(uint32_t* r, uint32_t addr) {
    asm volatile("ldmatrix.sync.aligned.m8n8.x4.shared.b16 {%0,%1,%2,%3}, [%4];"
                 : "=r"(r[0]), "=r"(r[1]), "=r"(r[2]), "=r"(r[3]) : "r"(addr));
}

static __device__ __forceinline__ void mma16816(float* c, const uint32_t* a,
                                                uint32_t b0, uint32_t b1) {
    asm volatile(
        "mma.sync.aligned.m16n8k16.row.col.f32.bf16.bf16.f32 "
        "{%0,%1,%2,%3}, {%4,%5,%6,%7}, {%8,%9}, {%0,%1,%2,%3};"
        : "+f"(c[0]), "+f"(c[1]), "+f"(c[2]), "+f"(c[3])
        : "r"(a[0]), "r"(a[1]), "r"(a[2]), "r"(a[3]), "r"(b0), "r"(b1));
}

static __device__ __forceinline__ void cp_async16(uint32_t dst, const void* src) {
    asm volatile("cp.async.cg.shared.global [%0], [%1], 16;"
                 :: "r"(dst), "l"(src) : "memory");
}

// ---------------- kernel 1: normalize + positives + zero denom ----------------
__global__ void __launch_bounds__(256) prep_kernel(
    const float* __restrict__ ei, const float* __restrict__ ej)
{
    const int k = blockIdx.x;        // 0..4095
    const int tid = threadIdx.x;     // 256 threads

    const int zidx = k * 256 + tid;
    if (zidx < N2) g_denom[zidx] = 0.0f;

    const float* ai = ei + (size_t)k * DIM;
    const float* aj = ej + (size_t)k * DIM;
    float a0 = ai[tid], a1 = ai[tid + 256];
    float b0 = aj[tid], b1 = aj[tid + 256];

    float ni = a0 * a0 + a1 * a1;
    float nj = b0 * b0 + b1 * b1;
    float dd = a0 * b0 + a1 * b1;
    #pragma unroll
    for (int o = 16; o; o >>= 1) {
        ni += __shfl_xor_sync(0xffffffffu, ni, o);
        nj += __shfl_xor_sync(0xffffffffu, nj, o);
        dd += __shfl_xor_sync(0xffffffffu, dd, o);
    }
    __shared__ float sni[8], snj[8], sdd[8], bc[3];
    const int wid = tid >> 5, lid = tid & 31;
    if (lid == 0) { sni[wid] = ni; snj[wid] = nj; sdd[wid] = dd; }
    __syncthreads();
    if (wid == 0) {
        float x = (lid < 8) ? sni[lid] : 0.f;
        float y = (lid < 8) ? snj[lid] : 0.f;
        float z = (lid < 8) ? sdd[lid] : 0.f;
        #pragma unroll
        for (int o = 4; o; o >>= 1) {
            x += __shfl_xor_sync(0xffffffffu, x, o);
            y += __shfl_xor_sync(0xffffffffu, y, o);
            z += __shfl_xor_sync(0xffffffffu, z, o);
        }
        if (lid == 0) { bc[0] = x; bc[1] = y; bc[2] = z; }
    }
    __syncthreads();
    const float rin = 1.0f / fmaxf(sqrtf(bc[0]), 1e-12f);
    const float rjn = 1.0f / fmaxf(sqrtf(bc[1]), 1e-12f);

    __nv_bfloat16* ri = g_reps + (size_t)k * DIM;
    __nv_bfloat16* rj = g_reps + (size_t)(BATCH + k) * DIM;
    ri[tid]       = __float2bfloat16(a0 * rin);
    ri[tid + 256] = __float2bfloat16(a1 * rin);
    rj[tid]       = __float2bfloat16(b0 * rjn);
    rj[tid + 256] = __float2bfloat16(b1 * rjn);
    if (tid == 0) g_pos[k] = bc[2] * rin * rjn;
}

// ---------------- kernel 2: symmetric tiled HMMA GEMM + fused exp sums ----------------
// Upper-triangular 128x128 tiles of sim = R R^T. Per CTA: 256 threads, 8 warps
// in 4(M)x2(N). BK=64, 3-stage cp.async pipeline, SW128-swizzled smem, ldmatrix
// fragment loads, mma.sync m16n8k16 bf16->fp32. Epilogue: exp(10*s), row sums
// always; column sums too on off-diagonal tiles (transpose contribution).
#define GT 256
#define STG 3
#define STAGE_BYTES 32768        // A(16KB) + B(16KB)
#define SMEM_BYTES  (STG * STAGE_BYTES + 1024)

__global__ void __launch_bounds__(GT) simexp_kernel()
{
    extern __shared__ char dynsmem[];
    const uint32_t base = (smem_u32(dynsmem) + 1023u) & ~1023u;

    const int tid  = threadIdx.x;
    const int wid  = tid >> 5;
    const int lane = tid & 31;
    const int warp_m = (wid & 3) * 32;   // 4 warps over M
    const int warp_n = (wid >> 2) * 64;  // 2 warps over N

    // triangular decode: tile (tm, tn), tn >= tm
    const int bid = blockIdx.x;
    int tm = (int)floorf((129.0f - sqrtf(129.0f * 129.0f - 8.0f * (float)bid)) * 0.5f);
    if (tm < 0) tm = 0;
    if (tm > NTILE - 1) tm = NTILE - 1;
    while ((tm + 1) * NTILE - ((tm + 1) * tm) / 2 <= bid) ++tm;
    while (tm * NTILE - (tm * (tm - 1)) / 2 > bid) --tm;
    const int tn = tm + (bid - (tm * NTILE - (tm * (tm - 1)) / 2));
    const bool diag = (tm == tn);

    const __nv_bfloat16* Abase = g_reps + (size_t)tm * 128 * DIM;
    const __nv_bfloat16* Bbase = g_reps + (size_t)tn * 128 * DIM;

    // ---- async load of K-chunk c into stage s ----
    auto load_stage = [&](int s, int c) {
        const uint32_t As = base + (uint32_t)s * STAGE_BYTES;
        const uint32_t Bs = As + 16384u;
        #pragma unroll
        for (int it = 0; it < 4; ++it) {
            const int id  = tid + it * GT;      // 0..1023
            const int row = id >> 3, kc = id & 7;
            const uint32_t off = sw128((uint32_t)(row * 128 + kc * 16));
            cp_async16(As + off, Abase + (size_t)row * DIM + c * 64 + kc * 8);
            cp_async16(Bs + off, Bbase + (size_t)row * DIM + c * 64 + kc * 8);
        }
    };

    float acc[2][8][4];
    #pragma unroll
    for (int mi = 0; mi < 2; ++mi)
        #pragma unroll
        for (int ni = 0; ni < 8; ++ni)
            #pragma unroll
            for (int e = 0; e < 4; ++e) acc[mi][ni][e] = 0.f;

    // prologue: chunks 0, 1
    load_stage(0, 0);
    asm volatile("cp.async.commit_group;" ::: "memory");
    load_stage(1, 1);
    asm volatile("cp.async.commit_group;" ::: "memory");

    for (int c = 0; c < 8; ++c) {
        asm volatile("cp.async.wait_group 1;" ::: "memory");
        __syncthreads();

        if (c + 2 < 8) load_stage((c + 2) % STG, c + 2);
        asm volatile("cp.async.commit_group;" ::: "memory");

        const uint32_t As = base + (uint32_t)((c % STG) * STAGE_BYTES);
        const uint32_t Bs = As + 16384u;

        #pragma unroll
        for (int ks = 0; ks < 4; ++ks) {   // 4 x k16 within BK=64
            uint32_t af[2][4], bf[4][4];
            #pragma unroll
            for (int mi = 0; mi < 2; ++mi) {
                const int row = warp_m + mi * 16 + (lane & 15);
                ldsm4(af[mi], As + sw128((uint32_t)(row * 128 + ks * 32 + (lane >> 4) * 16)));
            }
            #pragma unroll
            for (int p = 0; p < 4; ++p) {
                const int row = warp_n + p * 16 + (lane & 7) + ((lane >> 4) & 1) * 8;
                ldsm4(bf[p], Bs + sw128((uint32_t)(row * 128 + ks * 32 + ((lane >> 3) & 1) * 16)));
            }
            #pragma unroll
            for (int mi = 0; mi < 2; ++mi)
                #pragma unroll
                for (int ni = 0; ni < 8; ++ni)
                    mma16816(acc[mi][ni], af[mi],
                             bf[ni >> 1][(ni & 1) * 2], bf[ni >> 1][(ni & 1) * 2 + 1]);
        }
    }

    // ---- fused epilogue ----
    // C-frag map: c[2h+e] = (row = l/4 + 8h, col = 2*(l%4) + e)
    const int growb = tm * 128 + warp_m + (lane >> 2);
    const int gcolb = tn * 128 + warp_n + 2 * (lane & 3);

    float rsum[4] = {0.f, 0.f, 0.f, 0.f};       // [mi*2 + h]
    float csum[8][2];
    #pragma unroll
    for (int ni = 0; ni < 8; ++ni) { csum[ni][0] = 0.f; csum[ni][1] = 0.f; }

    #pragma unroll
    for (int mi = 0; mi < 2; ++mi)
        #pragma unroll
        for (int ni = 0; ni < 8; ++ni)
            #pragma unroll
            for (int h = 0; h < 2; ++h)
                #pragma unroll
                for (int e = 0; e < 2; ++e) {
                    float v = __expf(acc[mi][ni][2 * h + e] * INV_T);
                    if (diag && (growb + mi * 16 + h * 8 == gcolb + ni * 8 + e))
                        v = 0.f;   // exclude self-similarity
                    rsum[mi * 2 + h] += v;
                    csum[ni][e] += v;
                }

    // row sums: reduce over lanes sharing a row (lane bits 0,1)
    #pragma unroll
    for (int i = 0; i < 4; ++i) {
        rsum[i] += __shfl_xor_sync(0xffffffffu, rsum[i], 1);
        rsum[i] += __shfl_xor_sync(0xffffffffu, rsum[i], 2);
    }
    if ((lane & 3) == 0) {
        #pragma unroll
        for (int mi = 0; mi < 2; ++mi)
            #pragma unroll
            for (int h = 0; h < 2; ++h)
                atomicAdd(&g_denom[growb + mi * 16 + h * 8], rsum[mi * 2 + h]);
    }

    // column sums (transpose contribution) for off-diagonal tiles:
    // reduce over lanes sharing a column (lane bits 2,3,4)
    if (!diag) {
        #pragma unroll
        for (int ni = 0; ni < 8; ++ni)
            #pragma unroll
            for (int e = 0; e < 2; ++e) {
                float v = csum[ni][e];
                v += __shfl_xor_sync(0xffffffffu, v, 4);
                v += __shfl_xor_sync(0xffffffffu, v, 8);
                v += __shfl_xor_sync(0xffffffffu, v, 16);
                if ((lane >> 2) == 0)
                    atomicAdd(&g_denom[gcolb + ni * 8 + e], v);
            }
    }
}

// ---------------- kernel 3: final reduction ----------------
__global__ void __launch_bounds__(1024) finish_kernel(float* out, int out_size)
{
    const int tid = threadIdx.x;
    float sl = 0.f, sp = 0.f;
    for (int r = tid; r < N2; r += 1024) sl += logf(g_denom[r]);
    for (int k = tid; k < BATCH; k += 1024) sp += g_pos[k];

    #pragma unroll
    for (int o = 16; o; o >>= 1) {
        sl += __shfl_xor_sync(0xffffffffu, sl, o);
        sp += __shfl_xor_sync(0xffffffffu, sp, o);
    }
    __shared__ float rl[32], rp[32];
    const int wid = tid >> 5, lid = tid & 31;
    if (lid == 0) { rl[wid] = sl; rp[wid] = sp; }
    __syncthreads();
    if (wid == 0) {
        float x = rl[lid];
        float y = rp[lid];
        #pragma unroll
        for (int o = 16; o; o >>= 1) {
            x += __shfl_xor_sync(0xffffffffu, x, o);
            y += __shfl_xor_sync(0xffffffffu, y, o);
        }
        if (lid == 0) {
            const float loss = (x - 2.0f * y * INV_T) / (float)N2;
            for (int i = 0; i < out_size; ++i) out[i] = loss;
        }
    }
}

// ---------------- launch ----------------
extern "C" void kernel_launch(void* const* d_in, const int* in_sizes, int n_in,
                              void* d_out, int out_size)
{
    (void)in_sizes; (void)n_in;
    const float* ei = (const float*)d_in[0];
    const float* ej = (const float*)d_in[1];

    cudaFuncSetAttribute(simexp_kernel,
                         cudaFuncAttributeMaxDynamicSharedMemorySize, SMEM_BYTES);

    prep_kernel<<<BATCH, 256>>>(ei, ej);
    simexp_kernel<<<NTRI, GT, SMEM_BYTES>>>();
    finish_kernel<<<1, 1024>>>((float*)d_out, out_size);
}